// round 11
// baseline (speedup 1.0000x reference)
#include <cuda_runtime.h>
#include <cstdint>

// ---------------------------------------------------------------------------
// SINDy layer: out[b, c] = sum_t Theta(z[b])[t] * (Xi*mask)[t, c]
// B=65536, Z=32, terms = 1 + 32 + 528 + 5984 = 6545.
//
// R11 design: triangular-run FFMA2 GEMV with duplicated-z SMEM tables.
//  - theta_t built by runs: pair product p=z_i*z_j held in regs across the
//    k-run; per term only 2 LDS.64 (dup'd z_k for each row) + 2 MUL2.
//  - z stored pre-duplicated: T0[a][l]=(z_r0,z_r0), T1[a][l]=(z_r1,z_r1)
//    -> no SPLIT/PACK movs, no idx table, no idx ALU in the hot loop.
//  - Thread = 2 rows x 32 cols: 32 FFMA2 + 2 MUL2 per term.
//  - 128 thr/CTA, 256 rows/CTA, grid 256, 2 CTA/SM (98.3 KB SMEM).
//  - Xi_eff streamed via cp.async double buffer (128-term / 16 KB chunks);
//    chunk-swap check sits BEFORE the FMA block so the branch retires early.
// ---------------------------------------------------------------------------

#define ZDIM 32
#define NT 6545
#define NTP 6656                       // padded: 52 * 128
#define CHUNK 128
#define NCH 52
#define XI_BUF 16384                   // 128 terms * 128 B
#define ROWS 256
#define THREADS 128

// SMEM layout (dynamic): [xi0][xi1][T0: 32x128 f32x2][T1: 32x128 f32x2]
#define OFF_XI0  0
#define OFF_XI1  16384
#define OFF_T0   32768
#define OFF_T1   65536
#define SMEM_TOTAL 98304

__device__ __align__(16) float g_xi_eff[NTP * ZDIM];

// ---------------- PTX helpers (non-volatile: ptxas schedules freely) -------
#define FMA2(d, a, b, c) \
    asm("fma.rn.f32x2 %0, %1, %2, %3;" : "=l"(d) : "l"(a), "l"(b), "l"(c))
#define MUL2(d, a, b) \
    asm("mul.rn.f32x2 %0, %1, %2;" : "=l"(d) : "l"(a), "l"(b))
#define UNPACK2(x, y, p) \
    asm("mov.b64 {%0, %1}, %2;" : "=f"(x), "=f"(y) : "l"(p))

#define CP_ASYNC16(dst_u32, src_ptr) \
    asm volatile("cp.async.cg.shared.global [%0], [%1], 16;" \
                 :: "r"(dst_u32), "l"(src_ptr) : "memory")
#define CP_COMMIT() asm volatile("cp.async.commit_group;" ::: "memory")
#define CP_WAIT(N)  asm volatile("cp.async.wait_group %0;" :: "n"(N) : "memory")

// Stage one 128-term (16 KB) Xi chunk into buffer (c&1). 8 x 16B per thread.
#define STAGE(c) do {                                                        \
    uint32_t _dst = sbase + (((c) & 1) ? (uint32_t)OFF_XI1 : (uint32_t)OFF_XI0); \
    const float4* _xs = (const float4*)g_xi_eff + (c) * (CHUNK * 8);         \
    _Pragma("unroll")                                                        \
    for (int _u = 0; _u < 8; _u++) {                                         \
        int _q = _u * THREADS + tid;                                         \
        CP_ASYNC16(_dst + 16u * (uint32_t)_q, _xs + _q);                     \
    }                                                                        \
    CP_COMMIT();                                                             \
} while (0)

// One term: load xi quads + maybe-swap FIRST (branch retires while the
// previous term's FMAs drain), then the 32-FFMA2 block.
#define XI_TERM(t00v, t11v) do {                                             \
    const ulonglong2* _xt = (const ulonglong2*)(smem + xi_off);              \
    ulonglong2 _q0 = _xt[0], _q1 = _xt[1], _q2 = _xt[2], _q3 = _xt[3];       \
    ulonglong2 _q4 = _xt[4], _q5 = _xt[5], _q6 = _xt[6], _q7 = _xt[7];       \
    if (--rem == 0) {                 /* uniform across the block */         \
        __syncthreads();                                                     \
        ++ch;                                                                \
        if (ch + 1 < NCH) { STAGE(ch + 1); CP_WAIT(1); }                     \
        else              { CP_WAIT(0); }                                    \
        __syncthreads();                                                     \
        xi_off = (ch & 1) ? (uint32_t)OFF_XI1 : (uint32_t)OFF_XI0;           \
        rem = CHUNK;                                                         \
    } else {                                                                 \
        xi_off += 128u;                                                      \
    }                                                                        \
    FMA2(acc0[ 0], (t00v), _q0.x, acc0[ 0]); FMA2(acc1[ 0], (t11v), _q0.x, acc1[ 0]); \
    FMA2(acc0[ 1], (t00v), _q0.y, acc0[ 1]); FMA2(acc1[ 1], (t11v), _q0.y, acc1[ 1]); \
    FMA2(acc0[ 2], (t00v), _q1.x, acc0[ 2]); FMA2(acc1[ 2], (t11v), _q1.x, acc1[ 2]); \
    FMA2(acc0[ 3], (t00v), _q1.y, acc0[ 3]); FMA2(acc1[ 3], (t11v), _q1.y, acc1[ 3]); \
    FMA2(acc0[ 4], (t00v), _q2.x, acc0[ 4]); FMA2(acc1[ 4], (t11v), _q2.x, acc1[ 4]); \
    FMA2(acc0[ 5], (t00v), _q2.y, acc0[ 5]); FMA2(acc1[ 5], (t11v), _q2.y, acc1[ 5]); \
    FMA2(acc0[ 6], (t00v), _q3.x, acc0[ 6]); FMA2(acc1[ 6], (t11v), _q3.x, acc1[ 6]); \
    FMA2(acc0[ 7], (t00v), _q3.y, acc0[ 7]); FMA2(acc1[ 7], (t11v), _q3.y, acc1[ 7]); \
    FMA2(acc0[ 8], (t00v), _q4.x, acc0[ 8]); FMA2(acc1[ 8], (t11v), _q4.x, acc1[ 8]); \
    FMA2(acc0[ 9], (t00v), _q4.y, acc0[ 9]); FMA2(acc1[ 9], (t11v), _q4.y, acc1[ 9]); \
    FMA2(acc0[10], (t00v), _q5.x, acc0[10]); FMA2(acc1[10], (t11v), _q5.x, acc1[10]); \
    FMA2(acc0[11], (t00v), _q5.y, acc0[11]); FMA2(acc1[11], (t11v), _q5.y, acc1[11]); \
    FMA2(acc0[12], (t00v), _q6.x, acc0[12]); FMA2(acc1[12], (t11v), _q6.x, acc1[12]); \
    FMA2(acc0[13], (t00v), _q6.y, acc0[13]); FMA2(acc1[13], (t11v), _q6.y, acc1[13]); \
    FMA2(acc0[14], (t00v), _q7.x, acc0[14]); FMA2(acc1[14], (t11v), _q7.x, acc1[14]); \
    FMA2(acc0[15], (t00v), _q7.y, acc0[15]); FMA2(acc1[15], (t11v), _q7.y, acc1[15]); \
} while (0)

// ---------------- prep: Xi_eff = Xi * mask (zero-padded tail) --------------
__global__ void prep_kernel(const float* __restrict__ Xi,
                            const float* __restrict__ mask) {
    int i = blockIdx.x * blockDim.x + threadIdx.x;
    if (i < NTP * ZDIM)
        g_xi_eff[i] = (i < NT * ZDIM) ? Xi[i] * mask[i] : 0.f;
}

// ---------------- main kernel ----------------------------------------------
__global__ void __launch_bounds__(THREADS, 2)
sindy_kernel(const float* __restrict__ z, float* __restrict__ out) {
    extern __shared__ __align__(16) char smem[];
    const int tid = threadIdx.x;
    const int cta = blockIdx.x;
    const uint32_t sbase = (uint32_t)__cvta_generic_to_shared(smem);

    // Prefetch first two Xi chunks (overlaps z staging).
    STAGE(0);
    STAGE(1);

    // Stage duplicated z tables: T0[a][l]=(z_r0[a],z_r0[a]), T1 likewise for
    // row l+128. Thread t owns rows (cta*256 + t) and (+128).
    {
        float2* t0 = (float2*)(smem + OFF_T0);
        float2* t1 = (float2*)(smem + OFF_T1);
        const float4* r0 = (const float4*)z + ((size_t)cta * ROWS + tid) * 8;
        const float4* r1 = r0 + 128 * 8;
        #pragma unroll
        for (int u = 0; u < 8; u++) {
            float4 a = r0[u];
            float4 b = r1[u];
            t0[(u * 4 + 0) * 128 + tid] = make_float2(a.x, a.x);
            t0[(u * 4 + 1) * 128 + tid] = make_float2(a.y, a.y);
            t0[(u * 4 + 2) * 128 + tid] = make_float2(a.z, a.z);
            t0[(u * 4 + 3) * 128 + tid] = make_float2(a.w, a.w);
            t1[(u * 4 + 0) * 128 + tid] = make_float2(b.x, b.x);
            t1[(u * 4 + 1) * 128 + tid] = make_float2(b.y, b.y);
            t1[(u * 4 + 2) * 128 + tid] = make_float2(b.z, b.z);
            t1[(u * 4 + 3) * 128 + tid] = make_float2(b.w, b.w);
        }
    }

    CP_WAIT(1);        // chunk 0 resident
    __syncthreads();   // z tables + chunk 0 visible

    unsigned long long acc0[16], acc1[16];
    #pragma unroll
    for (int m = 0; m < 16; m++) { acc0[m] = 0ull; acc1[m] = 0ull; }

    uint32_t xi_off = (uint32_t)OFF_XI0;
    int rem = CHUNK;
    int ch = 0;

    // dup'd z pair streams: t0p[a<<7] = (z_r0[a], z_r0[a])
    const unsigned long long* t0p = (const unsigned long long*)(smem + OFF_T0) + tid;
    const unsigned long long* t1p = (const unsigned long long*)(smem + OFF_T1) + tid;

    // ---- term stream, exactly matching Xi row order ----
    // bias: theta = 1
    {
        unsigned long long one;
        asm("mov.b64 %0, {%1, %1};" : "=l"(one) : "r"(0x3f800000u));
        XI_TERM(one, one);
    }
    // linear: theta = z_k
    #pragma unroll 1
    for (int k = 0; k < ZDIM; k++) {
        XI_TERM(t0p[k << 7], t1p[k << 7]);
    }
    // quadratic: theta = z_i * z_k (i <= k), z_i held in regs per run
    #pragma unroll 1
    for (int i = 0; i < ZDIM; i++) {
        unsigned long long a0 = t0p[i << 7], a1 = t1p[i << 7];
        #pragma unroll 2
        for (int k = i; k < ZDIM; k++) {
            unsigned long long th0, th1;
            MUL2(th0, a0, t0p[k << 7]);
            MUL2(th1, a1, t1p[k << 7]);
            XI_TERM(th0, th1);
        }
    }
    // cubic: theta = z_i * z_j * z_k (i <= j <= k), pair product per run
    #pragma unroll 1
    for (int i = 0; i < ZDIM; i++) {
        unsigned long long a0 = t0p[i << 7], a1 = t1p[i << 7];
        #pragma unroll 1
        for (int j = i; j < ZDIM; j++) {
            unsigned long long p0, p1;
            MUL2(p0, a0, t0p[j << 7]);
            MUL2(p1, a1, t1p[j << 7]);
            #pragma unroll 2
            for (int k = j; k < ZDIM; k++) {
                unsigned long long th0, th1;
                MUL2(th0, p0, t0p[k << 7]);
                MUL2(th1, p1, t1p[k << 7]);
                XI_TERM(th0, th1);
            }
        }
    }

    // ---- epilogue: 2 rows x 32 cols per thread ----
    size_t r0 = (size_t)cta * ROWS + tid;
    float4* o0 = (float4*)(out + r0 * ZDIM);
    float4* o1 = (float4*)(out + (r0 + 128) * ZDIM);
    #pragma unroll
    for (int q = 0; q < 8; q++) {
        float4 v;
        UNPACK2(v.x, v.y, acc0[2 * q]);
        UNPACK2(v.z, v.w, acc0[2 * q + 1]);
        o0[q] = v;
    }
    #pragma unroll
    for (int q = 0; q < 8; q++) {
        float4 v;
        UNPACK2(v.x, v.y, acc1[2 * q]);
        UNPACK2(v.z, v.w, acc1[2 * q + 1]);
        o1[q] = v;
    }
}

// ---------------- launch ----------------------------------------------------
extern "C" void kernel_launch(void* const* d_in, const int* in_sizes, int n_in,
                              void* d_out, int out_size) {
    (void)in_sizes; (void)n_in; (void)out_size;
    const float* z    = (const float*)d_in[0];  // [65536, 32]
    const float* Xi   = (const float*)d_in[1];  // [6545, 32]
    const float* mask = (const float*)d_in[2];  // [6545, 32]
    // d_in[3] (z_mean) and d_in[4] (z_std) are unused by the reference.
    float* out = (float*)d_out;                 // [65536, 32]

    prep_kernel<<<(NTP * ZDIM + 255) / 256, 256>>>(Xi, mask);

    (void)cudaFuncSetAttribute(sindy_kernel,
                               cudaFuncAttributeMaxDynamicSharedMemorySize,
                               SMEM_TOTAL);
    sindy_kernel<<<65536 / ROWS, THREADS, SMEM_TOTAL>>>(z, out);
}

// round 12
// speedup vs baseline: 1.0747x; 1.0747x over previous
#include <cuda_runtime.h>
#include <cstdint>

// ---------------------------------------------------------------------------
// SINDy layer: out[b, c] = sum_t Theta(z[b])[t] * (Xi*mask)[t, c]
// B=65536, Z=32, terms = 1 + 32 + 528 + 5984 = 6545 (padded to 6656).
//
// R12 design = R10 (branch-free index-table FFMA2 GEMV, theta operands
// software-pipelined one term ahead) + explicit REGISTER double-buffer of the
// Xi quads: term t+1's 8 LDS.128 issue before term t's 32-FFMA2 block, so the
// 29-cyc LDS latency is fully covered (regs are free: 256 thr/SM only).
//  - Thread = 2 rows x 32 cols: 32 FFMA2 + 2 MUL2 (packed f32x2) per term.
//  - 128 thr/CTA, 256 rows/CTA, grid 256, 2 CTA/SM.
//  - Xi_eff + idx streamed via cp.async double buffer (256-term chunks).
// ---------------------------------------------------------------------------

#define ZDIM 32
#define NT 6545
#define NTP 6656                       // padded: 26 * 256
#define CHUNK 256
#define NCH 26
#define XI_BUF 32768                   // 256 terms * 128 B
#define IDX_BUF 1024                   // 256 terms * 4 B
#define ROWS 256
#define THREADS 128

// SMEM layout (dynamic): [xi0][xi1][idx0][idx1][z: 33 x 128 x float2]
#define OFF_XI0  0
#define OFF_XI1  32768
#define OFF_IDX  65536                 // + buf*1024
#define OFF_Z    67584
#define SMEM_TOTAL (67584 + 33 * 128 * 8)   // 101376

__device__ __align__(16) float    g_xi_eff[NTP * ZDIM];
__device__ __align__(16) unsigned g_idx[NTP];

// ---------------- PTX helpers (non-volatile: ptxas schedules freely) -------
#define FMA2(d, a, b, c) \
    asm("fma.rn.f32x2 %0, %1, %2, %3;" : "=l"(d) : "l"(a), "l"(b), "l"(c))
#define MUL2(d, a, b) \
    asm("mul.rn.f32x2 %0, %1, %2;" : "=l"(d) : "l"(a), "l"(b))
#define PACK2(d, s) \
    asm("mov.b64 %0, {%1, %1};" : "=l"(d) : "r"(s))
#define SPLIT2(lo, hi, p) \
    asm("mov.b64 {%0, %1}, %2;" : "=r"(lo), "=r"(hi) : "l"(p))
#define UNPACK2(x, y, p) \
    asm("mov.b64 {%0, %1}, %2;" : "=f"(x), "=f"(y) : "l"(p))

#define CP_ASYNC16(dst_u32, src_ptr) \
    asm volatile("cp.async.cg.shared.global [%0], [%1], 16;" \
                 :: "r"(dst_u32), "l"(src_ptr) : "memory")
#define CP_COMMIT() asm volatile("cp.async.commit_group;" ::: "memory")
#define CP_WAIT(N)  asm volatile("cp.async.wait_group %0;" :: "n"(N) : "memory")

// Stage chunk c (Xi 32 KB + idx 1 KB) into buffer (c&1). One commit group.
#define STAGE(c) do {                                                        \
    int _buf = (c) & 1;                                                      \
    uint32_t _dx = sbase + (_buf ? (uint32_t)OFF_XI1 : (uint32_t)OFF_XI0);   \
    const float4* _xs = (const float4*)g_xi_eff + (c) * (CHUNK * 8);         \
    _Pragma("unroll")                                                        \
    for (int _u = 0; _u < 16; _u++) {                                        \
        int _q = _u * THREADS + tid;                                         \
        CP_ASYNC16(_dx + 16u * (uint32_t)_q, _xs + _q);                      \
    }                                                                        \
    if (tid < 64) {                                                          \
        const float4* _is = (const float4*)g_idx + (c) * 64 + tid;           \
        CP_ASYNC16(sbase + (uint32_t)OFF_IDX + (uint32_t)(_buf * IDX_BUF)    \
                   + 16u * (uint32_t)tid, _is);                              \
    }                                                                        \
    CP_COMMIT();                                                             \
} while (0)

// ---------------- prep: Xi_eff = Xi * mask, plus idx table -----------------
__global__ void prep_kernel(const float* __restrict__ Xi,
                            const float* __restrict__ mask) {
    if (blockIdx.x < 832) {
        int i = blockIdx.x * 256 + threadIdx.x;
        if (i < NTP * ZDIM)
            g_xi_eff[i] = (i < NT * ZDIM) ? Xi[i] * mask[i] : 0.f;
        return;
    }
    int t = threadIdx.x;
    if (t >= 64) return;
    if (t < 32) {
        int i = t;
        int pos = 33 + 32 * i - (i * (i - 1)) / 2;          // quadratic rows
        for (int j = i; j < 32; j++)
            g_idx[pos++] = (unsigned)i | ((unsigned)j << 8) | (32u << 16);
        int cpos = 561;                                      // cubic rows
        for (int a = 0; a < i; a++) cpos += ((32 - a) * (33 - a)) / 2;
        for (int j = i; j < 32; j++)
            for (int k = j; k < 32; k++)
                g_idx[cpos++] = (unsigned)i | ((unsigned)j << 8) | ((unsigned)k << 16);
    } else if (t == 32) {
        g_idx[0] = 32u | (32u << 8) | (32u << 16);          // bias
        for (int k = 0; k < 32; k++)                         // linear
            g_idx[1 + k] = (unsigned)k | (32u << 8) | (32u << 16);
    } else {
        for (int p = NT + (t - 33); p < NTP; p += 31)        // pad tail
            g_idx[p] = 32u | (32u << 8) | (32u << 16);
    }
}

// ---------------- main kernel ----------------------------------------------
__global__ void __launch_bounds__(THREADS, 2)
sindy_kernel(const float* __restrict__ z, float* __restrict__ out) {
    extern __shared__ __align__(16) char smem[];
    const int tid = threadIdx.x;
    const int cta = blockIdx.x;
    const uint32_t sbase = (uint32_t)__cvta_generic_to_shared(smem);

    // Prefetch first two Xi/idx chunks (overlaps z staging).
    STAGE(0);
    STAGE(1);

    // Stage z as packed row-pairs: zz[a*128 + l] = (z[base+l][a], z[base+128+l][a]),
    // plus sentinel row a=32 of (1,1). Thread t owns rows t and t+128.
    {
        float* zs = (float*)(smem + OFF_Z);
        const float4* r0 = (const float4*)z + ((size_t)cta * ROWS + tid) * 8;
        const float4* r1 = r0 + 128 * 8;
        #pragma unroll
        for (int u = 0; u < 8; u++) {
            float4 a = r0[u];
            float4 b = r1[u];
            float2* zp = (float2*)zs;
            zp[(u * 4 + 0) * 128 + tid] = make_float2(a.x, b.x);
            zp[(u * 4 + 1) * 128 + tid] = make_float2(a.y, b.y);
            zp[(u * 4 + 2) * 128 + tid] = make_float2(a.z, b.z);
            zp[(u * 4 + 3) * 128 + tid] = make_float2(a.w, b.w);
        }
        ((float2*)zs)[32 * 128 + tid] = make_float2(1.f, 1.f);
    }

    CP_WAIT(1);        // chunk 0 resident
    __syncthreads();   // z + chunk 0 visible

    unsigned long long acc0[16], acc1[16];
    #pragma unroll
    for (int m = 0; m < 16; m++) { acc0[m] = 0ull; acc1[m] = 0ull; }

    const unsigned long long* zz =
        (const unsigned long long*)(smem + OFF_Z) + tid;

    for (int ch = 0; ch < NCH; ch++) {
        const int buf = ch & 1;
        const ulonglong2* xb =
            (const ulonglong2*)(smem + (buf ? OFF_XI1 : OFF_XI0));
        const unsigned* idxp = (const unsigned*)(smem + OFF_IDX + buf * IDX_BUF);

        // ---- software pipeline prologue: term 0's theta operands + Xi quads
        unsigned p0 = idxp[0];
        unsigned long long za = zz[(p0 & 255u) << 7];
        unsigned long long zb = zz[((p0 >> 8) & 255u) << 7];
        unsigned long long zc = zz[(p0 >> 16) << 7];
        ulonglong2 cq[8];
        #pragma unroll
        for (int m = 0; m < 8; m++) cq[m] = xb[m];

        #pragma unroll 2
        for (int t = 0; t < CHUNK; t++) {
            // theta for current term (operands already in regs)
            unsigned long long th;
            MUL2(th, za, zb);
            MUL2(th, th, zc);

            // prefetch next term's theta operands (wrap-masked, branch-free)
            unsigned pn = idxp[(t + 1) & (CHUNK - 1)];
            za = zz[(pn & 255u) << 7];
            zb = zz[((pn >> 8) & 255u) << 7];
            zc = zz[(pn >> 16) << 7];

            // prefetch next term's Xi quads into the spare register set
            const ulonglong2* xn = xb + (((t + 1) & (CHUNK - 1)) << 3);
            ulonglong2 nq[8];
            #pragma unroll
            for (int m = 0; m < 8; m++) nq[m] = xn[m];

            unsigned lo, hi;
            SPLIT2(lo, hi, th);
            unsigned long long t00, t11;
            PACK2(t00, lo);
            PACK2(t11, hi);

            FMA2(acc0[ 0], t00, cq[0].x, acc0[ 0]); FMA2(acc1[ 0], t11, cq[0].x, acc1[ 0]);
            FMA2(acc0[ 1], t00, cq[0].y, acc0[ 1]); FMA2(acc1[ 1], t11, cq[0].y, acc1[ 1]);
            FMA2(acc0[ 2], t00, cq[1].x, acc0[ 2]); FMA2(acc1[ 2], t11, cq[1].x, acc1[ 2]);
            FMA2(acc0[ 3], t00, cq[1].y, acc0[ 3]); FMA2(acc1[ 3], t11, cq[1].y, acc1[ 3]);
            FMA2(acc0[ 4], t00, cq[2].x, acc0[ 4]); FMA2(acc1[ 4], t11, cq[2].x, acc1[ 4]);
            FMA2(acc0[ 5], t00, cq[2].y, acc0[ 5]); FMA2(acc1[ 5], t11, cq[2].y, acc1[ 5]);
            FMA2(acc0[ 6], t00, cq[3].x, acc0[ 6]); FMA2(acc1[ 6], t11, cq[3].x, acc1[ 6]);
            FMA2(acc0[ 7], t00, cq[3].y, acc0[ 7]); FMA2(acc1[ 7], t11, cq[3].y, acc1[ 7]);
            FMA2(acc0[ 8], t00, cq[4].x, acc0[ 8]); FMA2(acc1[ 8], t11, cq[4].x, acc1[ 8]);
            FMA2(acc0[ 9], t00, cq[4].y, acc0[ 9]); FMA2(acc1[ 9], t11, cq[4].y, acc1[ 9]);
            FMA2(acc0[10], t00, cq[5].x, acc0[10]); FMA2(acc1[10], t11, cq[5].x, acc1[10]);
            FMA2(acc0[11], t00, cq[5].y, acc0[11]); FMA2(acc1[11], t11, cq[5].y, acc1[11]);
            FMA2(acc0[12], t00, cq[6].x, acc0[12]); FMA2(acc1[12], t11, cq[6].x, acc1[12]);
            FMA2(acc0[13], t00, cq[6].y, acc0[13]); FMA2(acc1[13], t11, cq[6].y, acc1[13]);
            FMA2(acc0[14], t00, cq[7].x, acc0[14]); FMA2(acc1[14], t11, cq[7].x, acc1[14]);
            FMA2(acc0[15], t00, cq[7].y, acc0[15]); FMA2(acc1[15], t11, cq[7].y, acc1[15]);

            // rotate register sets (renamed away under unroll 2)
            #pragma unroll
            for (int m = 0; m < 8; m++) cq[m] = nq[m];
        }

        __syncthreads();                 // all warps done reading buf
        if (ch + 2 < NCH) {
            STAGE(ch + 2);               // refill the buffer just drained
            CP_WAIT(1);                  // chunk ch+1 complete
        } else {
            CP_WAIT(0);
        }
        __syncthreads();                 // staged data visible
    }

    // ---- epilogue: 2 rows x 32 cols per thread ----
    size_t r0 = (size_t)cta * ROWS + tid;
    float4* o0 = (float4*)(out + r0 * ZDIM);
    float4* o1 = (float4*)(out + (r0 + 128) * ZDIM);
    #pragma unroll
    for (int q = 0; q < 8; q++) {
        float4 v;
        UNPACK2(v.x, v.y, acc0[2 * q]);
        UNPACK2(v.z, v.w, acc0[2 * q + 1]);
        o0[q] = v;
    }
    #pragma unroll
    for (int q = 0; q < 8; q++) {
        float4 v;
        UNPACK2(v.x, v.y, acc1[2 * q]);
        UNPACK2(v.z, v.w, acc1[2 * q + 1]);
        o1[q] = v;
    }
}

// ---------------- launch ----------------------------------------------------
extern "C" void kernel_launch(void* const* d_in, const int* in_sizes, int n_in,
                              void* d_out, int out_size) {
    (void)in_sizes; (void)n_in; (void)out_size;
    const float* z    = (const float*)d_in[0];  // [65536, 32]
    const float* Xi   = (const float*)d_in[1];  // [6545, 32]
    const float* mask = (const float*)d_in[2];  // [6545, 32]
    // d_in[3] (z_mean) and d_in[4] (z_std) are unused by the reference.
    float* out = (float*)d_out;                 // [65536, 32]

    prep_kernel<<<833, 256>>>(Xi, mask);        // xi premask + idx table

    (void)cudaFuncSetAttribute(sindy_kernel,
                               cudaFuncAttributeMaxDynamicSharedMemorySize,
                               SMEM_TOTAL);
    sindy_kernel<<<65536 / ROWS, THREADS, SMEM_TOTAL>>>(z, out);
}

// round 13
// speedup vs baseline: 1.1852x; 1.1029x over previous
#include <cuda_runtime.h>
#include <cstdint>

// ---------------------------------------------------------------------------
// SINDy layer: out[b, c] = sum_t Theta(z[b])[t] * (Xi*mask)[t, c]
// B=65536, Z=32, terms = 6545 (padded to 6656 = 8 slices x 832).
//
// R13: persistent split-K FFMA2 GEMV.
//  - FFMA2 issues at rt=3 (RF banking: 3 even + 3 odd distinct regs), so the
//    kernel is bank-throughput-bound; the only lever is SMSP load balance.
//  - 296 persistent CTAs (2/SM), 2048 work items = (256-row tile, 832-term
//    K-slice), static stride. Busiest SMSP: 2 warps x 7 x 832 terms
//    (vs 6656 before) -> ~573 us compute floor.
//  - Partials to 64 MB __device__ scratch; deterministic reduce kernel.
//  - Inner loop = verified R10 core (idx table, theta prefetch 1 ahead),
//    208-term cp.async double-buffered chunks, sentinel idx entry.
// ---------------------------------------------------------------------------

#define ZDIM 32
#define NT 6545
#define NTP 6656
#define SLICES 8
#define TPS 832                        // terms per slice
#define CHUNK 208                      // 4 chunks per slice
#define NITEMS 2048                    // 256 row-tiles x 8 slices
#define GRID 296
#define THREADS 128
#define ROWS 256

// SMEM layout
#define XI_CB 26624                    // 208 * 128
#define OFF_XI0 0
#define OFF_XI1 26624
#define OFF_I0  53248                  // 832 B idx + 4 B sentinel (pad to 864)
#define OFF_I1  54112
#define OFF_Z   54976                  // 33 x 128 x 8 = 33792
#define SMEM_TOTAL (54976 + 33792)     // 88768

#define IDX_SAFE (32u | (32u << 8) | (32u << 16))

__device__ __align__(16) float    g_xi_eff[NTP * ZDIM];
__device__ __align__(16) unsigned g_idx[NTP];
__device__ __align__(16) float    g_part[SLICES * 65536 * ZDIM];  // 64 MB

// ---------------- PTX helpers ----------------
#define FMA2(d, a, b, c) \
    asm("fma.rn.f32x2 %0, %1, %2, %3;" : "=l"(d) : "l"(a), "l"(b), "l"(c))
#define MUL2(d, a, b) \
    asm("mul.rn.f32x2 %0, %1, %2;" : "=l"(d) : "l"(a), "l"(b))
#define PACK2(d, s) \
    asm("mov.b64 %0, {%1, %1};" : "=l"(d) : "r"(s))
#define SPLIT2(lo, hi, p) \
    asm("mov.b64 {%0, %1}, %2;" : "=r"(lo), "=r"(hi) : "l"(p))
#define UNPACK2(x, y, p) \
    asm("mov.b64 {%0, %1}, %2;" : "=f"(x), "=f"(y) : "l"(p))

#define CP_ASYNC16(dst_u32, src_ptr) \
    asm volatile("cp.async.cg.shared.global [%0], [%1], 16;" \
                 :: "r"(dst_u32), "l"(src_ptr) : "memory")
#define CP_COMMIT() asm volatile("cp.async.commit_group;" ::: "memory")
#define CP_WAIT(N)  asm volatile("cp.async.wait_group %0;" :: "n"(N) : "memory")

// Stage chunk ci (0..3) of slice starting at term kb into buffer (ci&1).
#define STAGE(kb, ci) do {                                                   \
    int _buf = (ci) & 1;                                                     \
    uint32_t _dx = sbase + (_buf ? (uint32_t)OFF_XI1 : (uint32_t)OFF_XI0);   \
    uint32_t _di = sbase + (_buf ? (uint32_t)OFF_I1  : (uint32_t)OFF_I0);    \
    const float4* _xs = (const float4*)g_xi_eff                              \
                        + ((size_t)(kb) + (size_t)(ci) * CHUNK) * 8;         \
    _Pragma("unroll")                                                        \
    for (int _u = 0; _u < 13; _u++) {                                        \
        int _q = _u * THREADS + tid;                                         \
        CP_ASYNC16(_dx + 16u * (uint32_t)_q, _xs + _q);                      \
    }                                                                        \
    if (tid < 52) {                                                          \
        const float4* _is = (const float4*)(g_idx + (kb) + (ci) * CHUNK)     \
                            + tid;                                           \
        CP_ASYNC16(_di + 16u * (uint32_t)tid, _is);                          \
    }                                                                        \
    if (tid == 64)                                                           \
        *(unsigned*)(smem + (_buf ? OFF_I1 : OFF_I0) + CHUNK * 4) = IDX_SAFE;\
    CP_COMMIT();                                                             \
} while (0)

// ---------------- prep: Xi_eff = Xi * mask, plus idx table -----------------
__global__ void prep_kernel(const float* __restrict__ Xi,
                            const float* __restrict__ mask) {
    if (blockIdx.x < 832) {
        int i = blockIdx.x * 256 + threadIdx.x;
        if (i < NTP * ZDIM)
            g_xi_eff[i] = (i < NT * ZDIM) ? Xi[i] * mask[i] : 0.f;
        return;
    }
    int t = threadIdx.x;
    if (t >= 64) return;
    if (t < 32) {
        int i = t;
        int pos = 33 + 32 * i - (i * (i - 1)) / 2;          // quadratic rows
        for (int j = i; j < 32; j++)
            g_idx[pos++] = (unsigned)i | ((unsigned)j << 8) | (32u << 16);
        int cpos = 561;                                      // cubic rows
        for (int a = 0; a < i; a++) cpos += ((32 - a) * (33 - a)) / 2;
        for (int j = i; j < 32; j++)
            for (int k = j; k < 32; k++)
                g_idx[cpos++] = (unsigned)i | ((unsigned)j << 8) | ((unsigned)k << 16);
    } else if (t == 32) {
        g_idx[0] = IDX_SAFE;                                 // bias
        for (int k = 0; k < 32; k++)                         // linear
            g_idx[1 + k] = (unsigned)k | (32u << 8) | (32u << 16);
    } else {
        for (int p = NT + (t - 33); p < NTP; p += 31)        // pad tail
            g_idx[p] = IDX_SAFE;
    }
}

// ---------------- main kernel ----------------------------------------------
__global__ void __launch_bounds__(THREADS, 2)
sindy_kernel(const float* __restrict__ z) {
    extern __shared__ __align__(16) char smem[];
    const int tid = threadIdx.x;
    const uint32_t sbase = (uint32_t)__cvta_generic_to_shared(smem);

    // sentinel z row a=32: (1,1) pairs; never overwritten by item staging
    ((float2*)(smem + OFF_Z))[32 * 128 + tid] = make_float2(1.f, 1.f);

    const unsigned long long* zz =
        (const unsigned long long*)(smem + OFF_Z) + tid;

    for (int it = blockIdx.x; it < NITEMS; it += GRID) {
        const int r = it & 255;          // row tile
        const int s = it >> 8;           // K slice
        const int kb = s * TPS;

        // kick off first two Xi/idx chunks of this slice
        STAGE(kb, 0);
        STAGE(kb, 1);

        // stage z row-pairs for rows [r*256, r*256+256)
        {
            float2* zp = (float2*)(smem + OFF_Z);
            const float4* r0 = (const float4*)z + ((size_t)r * ROWS + tid) * 8;
            const float4* r1 = r0 + 128 * 8;
            #pragma unroll
            for (int u = 0; u < 8; u++) {
                float4 a = r0[u];
                float4 b = r1[u];
                zp[(u * 4 + 0) * 128 + tid] = make_float2(a.x, b.x);
                zp[(u * 4 + 1) * 128 + tid] = make_float2(a.y, b.y);
                zp[(u * 4 + 2) * 128 + tid] = make_float2(a.z, b.z);
                zp[(u * 4 + 3) * 128 + tid] = make_float2(a.w, b.w);
            }
        }

        CP_WAIT(1);        // chunk 0 resident
        __syncthreads();   // z + chunk 0 visible

        unsigned long long acc0[16], acc1[16];
        #pragma unroll
        for (int m = 0; m < 16; m++) { acc0[m] = 0ull; acc1[m] = 0ull; }

        for (int c = 0; c < 4; c++) {
            const int buf = c & 1;
            const ulonglong2* xb =
                (const ulonglong2*)(smem + (buf ? OFF_XI1 : OFF_XI0));
            const unsigned* idxp =
                (const unsigned*)(smem + (buf ? OFF_I1 : OFF_I0));

            // software pipeline: term 0's theta operands
            unsigned p0 = idxp[0];
            unsigned long long za = zz[(p0 & 255u) << 7];
            unsigned long long zb = zz[((p0 >> 8) & 255u) << 7];
            unsigned long long zc = zz[(p0 >> 16) << 7];

            #pragma unroll 2
            for (int t = 0; t < CHUNK; t++) {
                unsigned long long th;
                MUL2(th, za, zb);
                MUL2(th, th, zc);

                // next term's theta operands (t=207 reads the safe sentinel)
                unsigned pn = idxp[t + 1];
                za = zz[(pn & 255u) << 7];
                zb = zz[((pn >> 8) & 255u) << 7];
                zc = zz[(pn >> 16) << 7];

                unsigned lo, hi;
                SPLIT2(lo, hi, th);
                unsigned long long t00, t11;
                PACK2(t00, lo);
                PACK2(t11, hi);

                const ulonglong2* xt = xb + t * 8;
                ulonglong2 q0 = xt[0], q1 = xt[1], q2 = xt[2], q3 = xt[3];
                ulonglong2 q4 = xt[4], q5 = xt[5], q6 = xt[6], q7 = xt[7];

                FMA2(acc0[ 0], t00, q0.x, acc0[ 0]); FMA2(acc1[ 0], t11, q0.x, acc1[ 0]);
                FMA2(acc0[ 1], t00, q0.y, acc0[ 1]); FMA2(acc1[ 1], t11, q0.y, acc1[ 1]);
                FMA2(acc0[ 2], t00, q1.x, acc0[ 2]); FMA2(acc1[ 2], t11, q1.x, acc1[ 2]);
                FMA2(acc0[ 3], t00, q1.y, acc0[ 3]); FMA2(acc1[ 3], t11, q1.y, acc1[ 3]);
                FMA2(acc0[ 4], t00, q2.x, acc0[ 4]); FMA2(acc1[ 4], t11, q2.x, acc1[ 4]);
                FMA2(acc0[ 5], t00, q2.y, acc0[ 5]); FMA2(acc1[ 5], t11, q2.y, acc1[ 5]);
                FMA2(acc0[ 6], t00, q3.x, acc0[ 6]); FMA2(acc1[ 6], t11, q3.x, acc1[ 6]);
                FMA2(acc0[ 7], t00, q3.y, acc0[ 7]); FMA2(acc1[ 7], t11, q3.y, acc1[ 7]);
                FMA2(acc0[ 8], t00, q4.x, acc0[ 8]); FMA2(acc1[ 8], t11, q4.x, acc1[ 8]);
                FMA2(acc0[ 9], t00, q4.y, acc0[ 9]); FMA2(acc1[ 9], t11, q4.y, acc1[ 9]);
                FMA2(acc0[10], t00, q5.x, acc0[10]); FMA2(acc1[10], t11, q5.x, acc1[10]);
                FMA2(acc0[11], t00, q5.y, acc0[11]); FMA2(acc1[11], t11, q5.y, acc1[11]);
                FMA2(acc0[12], t00, q6.x, acc0[12]); FMA2(acc1[12], t11, q6.x, acc1[12]);
                FMA2(acc0[13], t00, q6.y, acc0[13]); FMA2(acc1[13], t11, q6.y, acc1[13]);
                FMA2(acc0[14], t00, q7.x, acc0[14]); FMA2(acc1[14], t11, q7.x, acc1[14]);
                FMA2(acc0[15], t00, q7.y, acc0[15]); FMA2(acc1[15], t11, q7.y, acc1[15]);
            }

            __syncthreads();               // all warps done with this buffer
            if (c < 2)      { STAGE(kb, c + 2); CP_WAIT(1); }
            else if (c == 2){ CP_WAIT(0); }
            __syncthreads();               // staged data visible / z reuse safe
        }

        // ---- epilogue: partial for this slice ----
        size_t row0 = (size_t)r * ROWS + tid;
        float* gp = g_part + ((size_t)s << 21);     // 65536*32 = 2^21
        float4* o0 = (float4*)(gp + row0 * ZDIM);
        float4* o1 = (float4*)(gp + (row0 + 128) * ZDIM);
        #pragma unroll
        for (int q = 0; q < 8; q++) {
            float4 v;
            UNPACK2(v.x, v.y, acc0[2 * q]);
            UNPACK2(v.z, v.w, acc0[2 * q + 1]);
            o0[q] = v;
        }
        #pragma unroll
        for (int q = 0; q < 8; q++) {
            float4 v;
            UNPACK2(v.x, v.y, acc1[2 * q]);
            UNPACK2(v.z, v.w, acc1[2 * q + 1]);
            o1[q] = v;
        }
    }
}

// ---------------- reduce: out = sum of 8 slice partials --------------------
__global__ void reduce_kernel(float* __restrict__ out) {
    int q = blockIdx.x * blockDim.x + threadIdx.x;       // float4 index
    const float4* p = (const float4*)g_part;
    float4 a = p[q];
    #pragma unroll
    for (int s = 1; s < SLICES; s++) {
        float4 b = p[(size_t)s * 524288 + q];
        a.x += b.x; a.y += b.y; a.z += b.z; a.w += b.w;
    }
    ((float4*)out)[q] = a;
}

// ---------------- launch ----------------------------------------------------
extern "C" void kernel_launch(void* const* d_in, const int* in_sizes, int n_in,
                              void* d_out, int out_size) {
    (void)in_sizes; (void)n_in; (void)out_size;
    const float* z    = (const float*)d_in[0];  // [65536, 32]
    const float* Xi   = (const float*)d_in[1];  // [6545, 32]
    const float* mask = (const float*)d_in[2];  // [6545, 32]
    // d_in[3] (z_mean) and d_in[4] (z_std) are unused by the reference.
    float* out = (float*)d_out;                 // [65536, 32]

    prep_kernel<<<833, 256>>>(Xi, mask);        // xi premask + idx table

    (void)cudaFuncSetAttribute(sindy_kernel,
                               cudaFuncAttributeMaxDynamicSharedMemorySize,
                               SMEM_TOTAL);
    sindy_kernel<<<GRID, THREADS, SMEM_TOTAL>>>(z);

    reduce_kernel<<<2048, 256>>>(out);
}